// round 2
// baseline (speedup 1.0000x reference)
#include <cuda_runtime.h>
#include <cuda_fp16.h>
#include <cstdint>

#define TDIM 2048
#define DMODEL 1024
#define NROWS 4096          // B*T = 2*2048
#define NHEAD 16
#define HDIM 64

// ---------------- scratch (device globals; no allocation allowed) ----------
__device__ __align__(16) __half g_xh   [NROWS * DMODEL];
__device__ __align__(16) __half g_wqkvh[DMODEL * 3 * DMODEL];
__device__ __align__(16) __half g_woh  [DMODEL * DMODEL];
__device__ __align__(16) __half g_qkvh [(size_t)NROWS * 3 * DMODEL];
__device__ __align__(16) __half g_yh   [NROWS * DMODEL];

// ---------------- small PTX helpers ----------------------------------------
__device__ __forceinline__ uint32_t smem_u32(const void* p) {
    return (uint32_t)__cvta_generic_to_shared(p);
}
__device__ __forceinline__ void cp_async16(uint32_t s, const void* g) {
    asm volatile("cp.async.cg.shared.global [%0], [%1], 16;" ::"r"(s), "l"(g));
}
__device__ __forceinline__ void cp_commit() {
    asm volatile("cp.async.commit_group;");
}
__device__ __forceinline__ void ldsm4(uint32_t& r0, uint32_t& r1, uint32_t& r2, uint32_t& r3, uint32_t a) {
    asm volatile("ldmatrix.sync.aligned.m8n8.x4.shared.b16 {%0,%1,%2,%3}, [%4];"
                 : "=r"(r0), "=r"(r1), "=r"(r2), "=r"(r3) : "r"(a));
}
__device__ __forceinline__ void ldsm4t(uint32_t& r0, uint32_t& r1, uint32_t& r2, uint32_t& r3, uint32_t a) {
    asm volatile("ldmatrix.sync.aligned.m8n8.x4.trans.shared.b16 {%0,%1,%2,%3}, [%4];"
                 : "=r"(r0), "=r"(r1), "=r"(r2), "=r"(r3) : "r"(a));
}
__device__ __forceinline__ void mma16816(float c[4], const uint32_t a[4], const uint32_t b[2]) {
    asm volatile(
        "mma.sync.aligned.m16n8k16.row.col.f32.f16.f16.f32 "
        "{%0,%1,%2,%3}, {%4,%5,%6,%7}, {%8,%9}, {%0,%1,%2,%3};"
        : "+f"(c[0]), "+f"(c[1]), "+f"(c[2]), "+f"(c[3])
        : "r"(a[0]), "r"(a[1]), "r"(a[2]), "r"(a[3]), "r"(b[0]), "r"(b[1]));
}

__device__ __forceinline__ void store2(__half* C, size_t idx, float a, float b) {
    *reinterpret_cast<__half2*>(C + idx) = __floats2half2_rn(a, b);
}
__device__ __forceinline__ void store2(float* C, size_t idx, float a, float b) {
    *reinterpret_cast<float2*>(C + idx) = make_float2(a, b);
}

// ---------------- fp32 -> fp16 conversion -----------------------------------
__global__ void cvt_kernel(const float4* __restrict__ s, __half2* __restrict__ d, int n4) {
    int i = blockIdx.x * blockDim.x + threadIdx.x;
    int stride = gridDim.x * blockDim.x;
    for (; i < n4; i += stride) {
        float4 v = s[i];
        d[2 * i]     = __floats2half2_rn(v.x, v.y);
        d[2 * i + 1] = __floats2half2_rn(v.z, v.w);
    }
}

// ---------------- generic fp16 GEMM: C[M,N] = A[M,K] * B[K,N] ---------------
// A,B row-major fp16.  128x128x32 CTA tile, 8 warps (2x4), warp tile 64x32.
template <typename OutT>
__global__ void __launch_bounds__(256) gemm_f16(
    const __half* __restrict__ A, const __half* __restrict__ B,
    OutT* __restrict__ C, int M, int N, int K)
{
    __shared__ __align__(16) __half sA[2][128][40];   // padded stride: LDSM conflict-free
    __shared__ __align__(16) __half sB[2][32][136];

    const int tid   = threadIdx.x;
    const int lane  = tid & 31;
    const int wid   = tid >> 5;
    const int warpM = wid >> 2;       // 0..1
    const int warpN = wid & 3;        // 0..3
    const int g  = lane >> 2, tg = lane & 3;
    const int bm = blockIdx.y * 128, bn = blockIdx.x * 128;

    float acc[4][4][4];
#pragma unroll
    for (int i = 0; i < 4; i++)
#pragma unroll
        for (int j = 0; j < 4; j++)
#pragma unroll
            for (int k = 0; k < 4; k++) acc[i][j][k] = 0.f;

    const int ar = tid >> 2, ac = (tid & 3) * 8;
    const int br = tid >> 4, bc = (tid & 15) * 8;

    const int KT = K >> 5;
    // prologue: stage 0
#pragma unroll
    for (int p = 0; p < 2; p++)
        cp_async16(smem_u32(&sA[0][ar + p * 64][ac]), A + (size_t)(bm + ar + p * 64) * K + ac);
#pragma unroll
    for (int p = 0; p < 2; p++)
        cp_async16(smem_u32(&sB[0][br + p * 16][bc]), B + (size_t)(br + p * 16) * N + bn + bc);
    cp_commit();

    for (int kt = 0; kt < KT; ++kt) {
        if (kt + 1 < KT) {
            const int st = (kt + 1) & 1, k0 = (kt + 1) * 32;
#pragma unroll
            for (int p = 0; p < 2; p++)
                cp_async16(smem_u32(&sA[st][ar + p * 64][ac]),
                           A + (size_t)(bm + ar + p * 64) * K + k0 + ac);
#pragma unroll
            for (int p = 0; p < 2; p++)
                cp_async16(smem_u32(&sB[st][br + p * 16][bc]),
                           B + (size_t)(k0 + br + p * 16) * N + bn + bc);
            cp_commit();
            asm volatile("cp.async.wait_group 1;");
        } else {
            asm volatile("cp.async.wait_group 0;");
        }
        __syncthreads();
        const int st = kt & 1;

#pragma unroll
        for (int ks = 0; ks < 2; ++ks) {
            uint32_t af[4][4], bf[4][2];
#pragma unroll
            for (int mi = 0; mi < 4; mi++) {
                int r = warpM * 64 + mi * 16 + (lane & 7) + ((lane >> 3) & 1) * 8;
                int c = ks * 16 + (lane >> 4) * 8;
                ldsm4(af[mi][0], af[mi][1], af[mi][2], af[mi][3], smem_u32(&sA[st][r][c]));
            }
#pragma unroll
            for (int pr = 0; pr < 2; pr++) {
                int r = ks * 16 + (lane & 7) + ((lane >> 3) & 1) * 8;
                int c = warpN * 32 + pr * 16 + (lane >> 4) * 8;
                ldsm4t(bf[2 * pr][0], bf[2 * pr][1], bf[2 * pr + 1][0], bf[2 * pr + 1][1],
                       smem_u32(&sB[st][r][c]));
            }
#pragma unroll
            for (int mi = 0; mi < 4; mi++)
#pragma unroll
                for (int ni = 0; ni < 4; ni++) mma16816(acc[mi][ni], af[mi], bf[ni]);
        }
        __syncthreads();
    }

    // epilogue
#pragma unroll
    for (int mi = 0; mi < 4; mi++) {
#pragma unroll
        for (int ni = 0; ni < 4; ni++) {
            int row = bm + warpM * 64 + mi * 16 + g;
            int col = bn + warpN * 32 + ni * 8 + 2 * tg;
            store2(C, (size_t)row * N + col, acc[mi][ni][0], acc[mi][ni][1]);
            store2(C, (size_t)(row + 8) * N + col, acc[mi][ni][2], acc[mi][ni][3]);
        }
    }
}

// ---------------- flash attention ------------------------------------------
// grid: (qtile=16, head=16, batch=2), 256 threads = 8 warps x 16 q-rows.
// q/k/v are slices of qkv[row][3*D]: q at h*64, k at D+h*64, v at 2D+h*64.
__global__ void attn_kernel(const __half* __restrict__ qkv, __half* __restrict__ y)
{
    __shared__ __align__(16) __half sK[2][64][72];
    __shared__ __align__(16) __half sV[2][64][72];

    const int tid = threadIdx.x, lane = tid & 31, wid = tid >> 5;
    const int g = lane >> 2, tg = lane & 3;
    const int h = blockIdx.y, b = blockIdx.z;
    const int q0 = blockIdx.x * 128;
    const size_t rb = (size_t)b * TDIM;
    const int qoff = h * HDIM, koff = DMODEL + h * HDIM, voff = 2 * DMODEL + h * HDIM;
    const int S3 = 3 * DMODEL;

    // ---- stage Q tile through sK, load Q fragments into registers ----
    uint32_t qa[4][4];
    {
        __half* qs = &sK[0][0][0];   // 128 rows * 72 halves = exactly sK's footprint
        const int r = tid >> 3, c = (tid & 7) * 8;
#pragma unroll
        for (int p = 0; p < 4; p++)
            cp_async16(smem_u32(qs + (size_t)(r + p * 32) * 72 + c),
                       qkv + (rb + q0 + r + p * 32) * S3 + qoff + c);
        cp_commit();
        asm volatile("cp.async.wait_group 0;");
        __syncthreads();
#pragma unroll
        for (int ks = 0; ks < 4; ks++) {
            int rr = wid * 16 + (lane & 7) + ((lane >> 3) & 1) * 8;
            int cc = ks * 16 + (lane >> 4) * 8;
            ldsm4(qa[ks][0], qa[ks][1], qa[ks][2], qa[ks][3],
                  smem_u32(qs + (size_t)rr * 72 + cc));
        }
        __syncthreads();
    }

    float o[8][4];
#pragma unroll
    for (int i = 0; i < 8; i++)
#pragma unroll
        for (int j = 0; j < 4; j++) o[i][j] = 0.f;
    float m0 = -1e30f, m1 = -1e30f, l0 = 0.f, l1 = 0.f;

    const int lr = tid >> 3, lc = (tid & 7) * 8;
    // prologue: kv tile 0
#pragma unroll
    for (int p = 0; p < 2; p++) {
        cp_async16(smem_u32(&sK[0][lr + p * 32][lc]), qkv + (rb + lr + p * 32) * S3 + koff + lc);
        cp_async16(smem_u32(&sV[0][lr + p * 32][lc]), qkv + (rb + lr + p * 32) * S3 + voff + lc);
    }
    cp_commit();

    const int NT = TDIM / 64;   // 32
    for (int it = 0; it < NT; ++it) {
        if (it + 1 < NT) {
            const int st = (it + 1) & 1, kv0 = (it + 1) * 64;
#pragma unroll
            for (int p = 0; p < 2; p++) {
                cp_async16(smem_u32(&sK[st][lr + p * 32][lc]),
                           qkv + (rb + kv0 + lr + p * 32) * S3 + koff + lc);
                cp_async16(smem_u32(&sV[st][lr + p * 32][lc]),
                           qkv + (rb + kv0 + lr + p * 32) * S3 + voff + lc);
            }
            cp_commit();
            asm volatile("cp.async.wait_group 1;");
        } else {
            asm volatile("cp.async.wait_group 0;");
        }
        __syncthreads();
        const int st = it & 1;

        // ---- S = Q * K^T  (16 q-rows x 64 kv per warp, fp32 accum) ----
        float s[8][4];
#pragma unroll
        for (int i = 0; i < 8; i++)
#pragma unroll
            for (int j = 0; j < 4; j++) s[i][j] = 0.f;

#pragma unroll
        for (int ks = 0; ks < 4; ks++) {
            uint32_t kb[8][2];
#pragma unroll
            for (int pr = 0; pr < 4; pr++) {
                int r = pr * 16 + (lane >> 4) * 8 + (lane & 7);
                int c = ks * 16 + ((lane >> 3) & 1) * 8;
                ldsm4(kb[2 * pr][0], kb[2 * pr][1], kb[2 * pr + 1][0], kb[2 * pr + 1][1],
                      smem_u32(&sK[st][r][c]));
            }
#pragma unroll
            for (int nt = 0; nt < 8; nt++) mma16816(s[nt], qa[ks], kb[nt]);
        }

        // ---- online softmax (exp2 space; cs = scale * log2(e)) ----
        const float cs = 0.18033688011112042f;   // (1/8) * log2(e)
        float mt0 = -1e30f, mt1 = -1e30f;
#pragma unroll
        for (int nt = 0; nt < 8; nt++) {
            mt0 = fmaxf(mt0, fmaxf(s[nt][0], s[nt][1]));
            mt1 = fmaxf(mt1, fmaxf(s[nt][2], s[nt][3]));
        }
        mt0 = fmaxf(mt0, __shfl_xor_sync(0xffffffffu, mt0, 1));
        mt0 = fmaxf(mt0, __shfl_xor_sync(0xffffffffu, mt0, 2));
        mt1 = fmaxf(mt1, __shfl_xor_sync(0xffffffffu, mt1, 1));
        mt1 = fmaxf(mt1, __shfl_xor_sync(0xffffffffu, mt1, 2));
        float mn0 = fmaxf(m0, mt0 * cs);
        float mn1 = fmaxf(m1, mt1 * cs);
        float a0 = exp2f(m0 - mn0), a1 = exp2f(m1 - mn1);
        float rs0 = 0.f, rs1 = 0.f;
        uint32_t pa[8][2];
#pragma unroll
        for (int nt = 0; nt < 8; nt++) {
            float p0 = exp2f(s[nt][0] * cs - mn0);
            float p1 = exp2f(s[nt][1] * cs - mn0);
            float p2 = exp2f(s[nt][2] * cs - mn1);
            float p3 = exp2f(s[nt][3] * cs - mn1);
            rs0 += p0 + p1;
            rs1 += p2 + p3;
            __half2 h01 = __floats2half2_rn(p0, p1);
            __half2 h23 = __floats2half2_rn(p2, p3);
            pa[nt][0] = *reinterpret_cast<uint32_t*>(&h01);
            pa[nt][1] = *reinterpret_cast<uint32_t*>(&h23);
        }
        m0 = mn0; m1 = mn1;
        l0 = l0 * a0 + rs0;
        l1 = l1 * a1 + rs1;
#pragma unroll
        for (int nt = 0; nt < 8; nt++) {
            o[nt][0] *= a0; o[nt][1] *= a0;
            o[nt][2] *= a1; o[nt][3] *= a1;
        }

        // ---- O += P * V (P fragments come straight from S accumulators) ----
#pragma unroll
        for (int ks = 0; ks < 4; ks++) {
            uint32_t ap[4] = { pa[2 * ks][0], pa[2 * ks][1], pa[2 * ks + 1][0], pa[2 * ks + 1][1] };
            uint32_t vb[8][2];
#pragma unroll
            for (int pr = 0; pr < 4; pr++) {
                int r = ks * 16 + ((lane >> 3) & 1) * 8 + (lane & 7);
                int c = pr * 16 + (lane >> 4) * 8;
                ldsm4t(vb[2 * pr][0], vb[2 * pr][1], vb[2 * pr + 1][0], vb[2 * pr + 1][1],
                       smem_u32(&sV[st][r][c]));
            }
#pragma unroll
            for (int nt = 0; nt < 8; nt++) mma16816(o[nt], ap, vb[nt]);
        }
        __syncthreads();
    }

    // ---- BUGFIX (R1->R2): l0/l1 were per-thread partial sums over this
    // thread's 16 of 64 kv columns; reduce across the 4 threads sharing a
    // q-row before normalizing (m was already reduced, so partials are
    // consistently scaled and just sum).
    l0 += __shfl_xor_sync(0xffffffffu, l0, 1);
    l0 += __shfl_xor_sync(0xffffffffu, l0, 2);
    l1 += __shfl_xor_sync(0xffffffffu, l1, 1);
    l1 += __shfl_xor_sync(0xffffffffu, l1, 2);

    // ---- normalize + write y (fp16) ----
    const float il0 = 1.f / l0, il1 = 1.f / l1;
#pragma unroll
    for (int nt = 0; nt < 8; nt++) {
        int row = q0 + wid * 16 + g;
        int col = h * HDIM + nt * 8 + 2 * tg;
        *reinterpret_cast<__half2*>(y + (rb + row) * DMODEL + col) =
            __floats2half2_rn(o[nt][0] * il0, o[nt][1] * il0);
        *reinterpret_cast<__half2*>(y + (rb + row + 8) * DMODEL + col) =
            __floats2half2_rn(o[nt][2] * il1, o[nt][3] * il1);
    }
}

// ---------------- launcher ---------------------------------------------------
extern "C" void kernel_launch(void* const* d_in, const int* in_sizes, int n_in,
                              void* d_out, int out_size)
{
    (void)in_sizes; (void)n_in; (void)out_size;
    const float* x    = (const float*)d_in[0];
    const float* wqkv = (const float*)d_in[1];
    const float* wo   = (const float*)d_in[2];
    float* out = (float*)d_out;

    __half *xh, *wqkvh, *woh, *qkvh, *yh;
    cudaGetSymbolAddress((void**)&xh,    g_xh);
    cudaGetSymbolAddress((void**)&wqkvh, g_wqkvh);
    cudaGetSymbolAddress((void**)&woh,   g_woh);
    cudaGetSymbolAddress((void**)&qkvh,  g_qkvh);
    cudaGetSymbolAddress((void**)&yh,    g_yh);

    cvt_kernel<<<512, 256>>>((const float4*)x,    (__half2*)xh,    NROWS * DMODEL / 4);
    cvt_kernel<<<512, 256>>>((const float4*)wqkv, (__half2*)wqkvh, DMODEL * 3 * DMODEL / 4);
    cvt_kernel<<<256, 256>>>((const float4*)wo,   (__half2*)woh,   DMODEL * DMODEL / 4);

    // qkv = x @ Wqkv : [4096,3072]
    gemm_f16<__half><<<dim3(3 * DMODEL / 128, NROWS / 128), 256>>>(
        xh, wqkvh, qkvh, NROWS, 3 * DMODEL, DMODEL);

    // flash attention -> y (fp16) [4096,1024]
    attn_kernel<<<dim3(TDIM / 128, NHEAD, 2), 256>>>(qkvh, yh);

    // out = y @ Wo : [4096,1024] fp32
    gemm_f16<float><<<dim3(DMODEL / 128, NROWS / 128), 256>>>(
        yh, woh, out, NROWS, DMODEL, DMODEL);
}

// round 3
// speedup vs baseline: 1.0061x; 1.0061x over previous
#include <cuda_runtime.h>
#include <cuda_fp16.h>
#include <cstdint>

#define TDIM 2048
#define DMODEL 1024
#define NROWS 4096          // B*T = 2*2048
#define NHEAD 16
#define HDIM 64

// ---------------- scratch (device globals; no allocation allowed) ----------
__device__ __align__(16) __half g_xh   [NROWS * DMODEL];
__device__ __align__(16) __half g_wqkvh[DMODEL * 3 * DMODEL];
__device__ __align__(16) __half g_woh  [DMODEL * DMODEL];
__device__ __align__(16) __half g_qkvh [(size_t)NROWS * 3 * DMODEL];
__device__ __align__(16) __half g_yh   [NROWS * DMODEL];

// ---------------- small PTX helpers ----------------------------------------
__device__ __forceinline__ uint32_t smem_u32(const void* p) {
    return (uint32_t)__cvta_generic_to_shared(p);
}
__device__ __forceinline__ void cp_async16(uint32_t s, const void* g) {
    asm volatile("cp.async.cg.shared.global [%0], [%1], 16;" ::"r"(s), "l"(g));
}
__device__ __forceinline__ void cp_commit() {
    asm volatile("cp.async.commit_group;");
}
__device__ __forceinline__ void ldsm4(uint32_t& r0, uint32_t& r1, uint32_t& r2, uint32_t& r3, uint32_t a) {
    asm volatile("ldmatrix.sync.aligned.m8n8.x4.shared.b16 {%0,%1,%2,%3}, [%4];"
                 : "=r"(r0), "=r"(r1), "=r"(r2), "=r"(r3) : "r"(a));
}
__device__ __forceinline__ void ldsm4t(uint32_t& r0, uint32_t& r1, uint32_t& r2, uint32_t& r3, uint32_t a) {
    asm volatile("ldmatrix.sync.aligned.m8n8.x4.trans.shared.b16 {%0,%1,%2,%3}, [%4];"
                 : "=r"(r0), "=r"(r1), "=r"(r2), "=r"(r3) : "r"(a));
}
__device__ __forceinline__ void mma16816(float c[4], const uint32_t a[4], const uint32_t b[2]) {
    asm volatile(
        "mma.sync.aligned.m16n8k16.row.col.f32.f16.f16.f32 "
        "{%0,%1,%2,%3}, {%4,%5,%6,%7}, {%8,%9}, {%0,%1,%2,%3};"
        : "+f"(c[0]), "+f"(c[1]), "+f"(c[2]), "+f"(c[3])
        : "r"(a[0]), "r"(a[1]), "r"(a[2]), "r"(a[3]), "r"(b[0]), "r"(b[1]));
}

__device__ __forceinline__ void store2(__half* C, size_t idx, float a, float b) {
    *reinterpret_cast<__half2*>(C + idx) = __floats2half2_rn(a, b);
}
__device__ __forceinline__ void store2(float* C, size_t idx, float a, float b) {
    *reinterpret_cast<float2*>(C + idx) = make_float2(a, b);
}

// ---------------- fp32 -> fp16 conversion -----------------------------------
__global__ void cvt_kernel(const float4* __restrict__ s, __half2* __restrict__ d, int n4) {
    int i = blockIdx.x * blockDim.x + threadIdx.x;
    int stride = gridDim.x * blockDim.x;
    for (; i < n4; i += stride) {
        float4 v = s[i];
        d[2 * i]     = __floats2half2_rn(v.x, v.y);
        d[2 * i + 1] = __floats2half2_rn(v.z, v.w);
    }
}

// ---------------- generic fp16 GEMM: C[M,N] = A[M,K] * B[K,N] ---------------
// A,B row-major fp16. 128x128x32 CTA tile, 8 warps (2x4), warp tile 64x32.
// 3-stage cp.async circular pipeline: ONE __syncthreads per k-iteration.
#define G_STAGES 3
// per-stage halves: A 128*40, B 32*136
#define GA_H (128 * 40)
#define GB_H (32 * 136)
#define GEMM_SMEM_BYTES (G_STAGES * (GA_H + GB_H) * 2)

template <typename OutT>
__global__ void __launch_bounds__(256) gemm_f16(
    const __half* __restrict__ A, const __half* __restrict__ B,
    OutT* __restrict__ C, int M, int N, int K)
{
    extern __shared__ __align__(16) __half smem[];
    __half* sA = smem;                       // [G_STAGES][128][40]
    __half* sB = smem + G_STAGES * GA_H;     // [G_STAGES][32][136]

    const int tid   = threadIdx.x;
    const int lane  = tid & 31;
    const int wid   = tid >> 5;
    const int warpM = wid >> 2;       // 0..1
    const int warpN = wid & 3;        // 0..3
    const int g  = lane >> 2, tg = lane & 3;
    const int bm = blockIdx.y * 128, bn = blockIdx.x * 128;

    float acc[4][4][4];
#pragma unroll
    for (int i = 0; i < 4; i++)
#pragma unroll
        for (int j = 0; j < 4; j++)
#pragma unroll
            for (int k = 0; k < 4; k++) acc[i][j][k] = 0.f;

    const int ar = tid >> 2, ac = (tid & 3) * 8;
    const int br = tid >> 4, bc = (tid & 15) * 8;

    const int KT = K >> 5;

    // prologue: stages 0 .. G_STAGES-2
#pragma unroll
    for (int st = 0; st < G_STAGES - 1; st++) {
        const int k0 = st * 32;
#pragma unroll
        for (int p = 0; p < 2; p++)
            cp_async16(smem_u32(sA + st * GA_H + (ar + p * 64) * 40 + ac),
                       A + (size_t)(bm + ar + p * 64) * K + k0 + ac);
#pragma unroll
        for (int p = 0; p < 2; p++)
            cp_async16(smem_u32(sB + st * GB_H + (br + p * 16) * 136 + bc),
                       B + (size_t)(k0 + br + p * 16) * N + bn + bc);
        cp_commit();
    }

    for (int kt = 0; kt < KT; ++kt) {
        asm volatile("cp.async.wait_group %0;" ::"n"(G_STAGES - 2));
        __syncthreads();

        // prefetch stage kt + G_STAGES-1 (overwrites buffer read in iter kt-1)
        {
            const int pf = kt + G_STAGES - 1;
            if (pf < KT) {
                const int st = pf % G_STAGES, k0 = pf * 32;
#pragma unroll
                for (int p = 0; p < 2; p++)
                    cp_async16(smem_u32(sA + st * GA_H + (ar + p * 64) * 40 + ac),
                               A + (size_t)(bm + ar + p * 64) * K + k0 + ac);
#pragma unroll
                for (int p = 0; p < 2; p++)
                    cp_async16(smem_u32(sB + st * GB_H + (br + p * 16) * 136 + bc),
                               B + (size_t)(k0 + br + p * 16) * N + bn + bc);
            }
            cp_commit();   // always commit (possibly empty) to keep group counting sound
        }

        const int st = kt % G_STAGES;
        const __half* cA = sA + st * GA_H;
        const __half* cB = sB + st * GB_H;

#pragma unroll
        for (int ks = 0; ks < 2; ++ks) {
            uint32_t af[4][4], bf[4][2];
#pragma unroll
            for (int mi = 0; mi < 4; mi++) {
                int r = warpM * 64 + mi * 16 + (lane & 7) + ((lane >> 3) & 1) * 8;
                int c = ks * 16 + (lane >> 4) * 8;
                ldsm4(af[mi][0], af[mi][1], af[mi][2], af[mi][3],
                      smem_u32(cA + r * 40 + c));
            }
#pragma unroll
            for (int pr = 0; pr < 2; pr++) {
                int r = ks * 16 + (lane & 7) + ((lane >> 3) & 1) * 8;
                int c = warpN * 32 + pr * 16 + (lane >> 4) * 8;
                ldsm4t(bf[2 * pr][0], bf[2 * pr][1], bf[2 * pr + 1][0], bf[2 * pr + 1][1],
                       smem_u32(cB + r * 136 + c));
            }
#pragma unroll
            for (int mi = 0; mi < 4; mi++)
#pragma unroll
                for (int ni = 0; ni < 4; ni++) mma16816(acc[mi][ni], af[mi], bf[ni]);
        }
    }

    // epilogue
#pragma unroll
    for (int mi = 0; mi < 4; mi++) {
#pragma unroll
        for (int ni = 0; ni < 4; ni++) {
            int row = bm + warpM * 64 + mi * 16 + g;
            int col = bn + warpN * 32 + ni * 8 + 2 * tg;
            store2(C, (size_t)row * N + col, acc[mi][ni][0], acc[mi][ni][1]);
            store2(C, (size_t)(row + 8) * N + col, acc[mi][ni][2], acc[mi][ni][3]);
        }
    }
}

// ---------------- flash attention ------------------------------------------
// grid: (qtile=16, head=16, batch=2), 256 threads = 8 warps x 16 q-rows.
// q/k/v are slices of qkv[row][3*D]: q at h*64, k at D+h*64, v at 2D+h*64.
// K/V: 3-stage cp.async pipeline, one __syncthreads per kv tile.
#define A_STAGES 3
#define AK_H (64 * 72)     // per-stage halves for K (same for V)
#define ATTN_SMEM_BYTES (A_STAGES * 2 * AK_H * 2)

__global__ void __launch_bounds__(256) attn_kernel(
    const __half* __restrict__ qkv, __half* __restrict__ y)
{
    extern __shared__ __align__(16) __half smem[];
    __half* sK = smem;                     // [A_STAGES][64][72]
    __half* sV = smem + A_STAGES * AK_H;   // [A_STAGES][64][72]

    const int tid = threadIdx.x, lane = tid & 31, wid = tid >> 5;
    const int g = lane >> 2, tg = lane & 3;
    const int h = blockIdx.y, b = blockIdx.z;
    const int q0 = blockIdx.x * 128;
    const size_t rb = (size_t)b * TDIM;
    const int qoff = h * HDIM, koff = DMODEL + h * HDIM, voff = 2 * DMODEL + h * HDIM;
    const int S3 = 3 * DMODEL;

    // ---- stage Q tile through sK area, load Q fragments into registers ----
    uint32_t qa[4][4];
    {
        __half* qs = sK;   // 128 rows * 72 halves fits in K stages 0..1
        const int r = tid >> 3, c = (tid & 7) * 8;
#pragma unroll
        for (int p = 0; p < 4; p++)
            cp_async16(smem_u32(qs + (r + p * 32) * 72 + c),
                       qkv + (rb + q0 + r + p * 32) * S3 + qoff + c);
        cp_commit();
        asm volatile("cp.async.wait_group 0;");
        __syncthreads();
#pragma unroll
        for (int ks = 0; ks < 4; ks++) {
            int rr = wid * 16 + (lane & 7) + ((lane >> 3) & 1) * 8;
            int cc = ks * 16 + (lane >> 4) * 8;
            ldsm4(qa[ks][0], qa[ks][1], qa[ks][2], qa[ks][3],
                  smem_u32(qs + rr * 72 + cc));
        }
        __syncthreads();   // everyone done reading Q before KV overwrites
    }

    float o[8][4];
#pragma unroll
    for (int i = 0; i < 8; i++)
#pragma unroll
        for (int j = 0; j < 4; j++) o[i][j] = 0.f;
    float m0 = -1e30f, m1 = -1e30f, l0 = 0.f, l1 = 0.f;

    const int lr = tid >> 3, lc = (tid & 7) * 8;
    // prologue: kv tiles 0 .. A_STAGES-2
#pragma unroll
    for (int st = 0; st < A_STAGES - 1; st++) {
        const int kv0 = st * 64;
#pragma unroll
        for (int p = 0; p < 2; p++) {
            cp_async16(smem_u32(sK + st * AK_H + (lr + p * 32) * 72 + lc),
                       qkv + (rb + kv0 + lr + p * 32) * S3 + koff + lc);
            cp_async16(smem_u32(sV + st * AK_H + (lr + p * 32) * 72 + lc),
                       qkv + (rb + kv0 + lr + p * 32) * S3 + voff + lc);
        }
        cp_commit();
    }

    const int NT = TDIM / 64;   // 32
    for (int it = 0; it < NT; ++it) {
        asm volatile("cp.async.wait_group %0;" ::"n"(A_STAGES - 2));
        __syncthreads();

        // prefetch kv tile it + A_STAGES-1
        {
            const int pf = it + A_STAGES - 1;
            if (pf < NT) {
                const int st = pf % A_STAGES, kv0 = pf * 64;
#pragma unroll
                for (int p = 0; p < 2; p++) {
                    cp_async16(smem_u32(sK + st * AK_H + (lr + p * 32) * 72 + lc),
                               qkv + (rb + kv0 + lr + p * 32) * S3 + koff + lc);
                    cp_async16(smem_u32(sV + st * AK_H + (lr + p * 32) * 72 + lc),
                               qkv + (rb + kv0 + lr + p * 32) * S3 + voff + lc);
                }
            }
            cp_commit();
        }

        const int st = it % A_STAGES;
        const __half* cK = sK + st * AK_H;
        const __half* cV = sV + st * AK_H;

        // ---- S = Q * K^T  (16 q-rows x 64 kv per warp, fp32 accum) ----
        float s[8][4];
#pragma unroll
        for (int i = 0; i < 8; i++)
#pragma unroll
            for (int j = 0; j < 4; j++) s[i][j] = 0.f;

#pragma unroll
        for (int ks = 0; ks < 4; ks++) {
            uint32_t kb[8][2];
#pragma unroll
            for (int pr = 0; pr < 4; pr++) {
                int r = pr * 16 + (lane >> 4) * 8 + (lane & 7);
                int c = ks * 16 + ((lane >> 3) & 1) * 8;
                ldsm4(kb[2 * pr][0], kb[2 * pr][1], kb[2 * pr + 1][0], kb[2 * pr + 1][1],
                      smem_u32(cK + r * 72 + c));
            }
#pragma unroll
            for (int nt = 0; nt < 8; nt++) mma16816(s[nt], qa[ks], kb[nt]);
        }

        // ---- online softmax (exp2 space; cs = scale * log2(e)) ----
        const float cs = 0.18033688011112042f;   // (1/8) * log2(e)
        float mt0 = -1e30f, mt1 = -1e30f;
#pragma unroll
        for (int nt = 0; nt < 8; nt++) {
            mt0 = fmaxf(mt0, fmaxf(s[nt][0], s[nt][1]));
            mt1 = fmaxf(mt1, fmaxf(s[nt][2], s[nt][3]));
        }
        mt0 = fmaxf(mt0, __shfl_xor_sync(0xffffffffu, mt0, 1));
        mt0 = fmaxf(mt0, __shfl_xor_sync(0xffffffffu, mt0, 2));
        mt1 = fmaxf(mt1, __shfl_xor_sync(0xffffffffu, mt1, 1));
        mt1 = fmaxf(mt1, __shfl_xor_sync(0xffffffffu, mt1, 2));
        float mn0 = fmaxf(m0, mt0 * cs);
        float mn1 = fmaxf(m1, mt1 * cs);
        float a0 = exp2f(m0 - mn0), a1 = exp2f(m1 - mn1);
        float rs0 = 0.f, rs1 = 0.f;
        uint32_t pa[8][2];
#pragma unroll
        for (int nt = 0; nt < 8; nt++) {
            float p0 = exp2f(s[nt][0] * cs - mn0);
            float p1 = exp2f(s[nt][1] * cs - mn0);
            float p2 = exp2f(s[nt][2] * cs - mn1);
            float p3 = exp2f(s[nt][3] * cs - mn1);
            rs0 += p0 + p1;
            rs1 += p2 + p3;
            __half2 h01 = __floats2half2_rn(p0, p1);
            __half2 h23 = __floats2half2_rn(p2, p3);
            pa[nt][0] = *reinterpret_cast<uint32_t*>(&h01);
            pa[nt][1] = *reinterpret_cast<uint32_t*>(&h23);
        }
        m0 = mn0; m1 = mn1;
        l0 = l0 * a0 + rs0;
        l1 = l1 * a1 + rs1;
#pragma unroll
        for (int nt = 0; nt < 8; nt++) {
            o[nt][0] *= a0; o[nt][1] *= a0;
            o[nt][2] *= a1; o[nt][3] *= a1;
        }

        // ---- O += P * V (P fragments come straight from S accumulators) ----
#pragma unroll
        for (int ks = 0; ks < 4; ks++) {
            uint32_t ap[4] = { pa[2 * ks][0], pa[2 * ks][1], pa[2 * ks + 1][0], pa[2 * ks + 1][1] };
            uint32_t vb[8][2];
#pragma unroll
            for (int pr = 0; pr < 4; pr++) {
                int r = ks * 16 + ((lane >> 3) & 1) * 8 + (lane & 7);
                int c = pr * 16 + (lane >> 4) * 8;
                ldsm4t(vb[2 * pr][0], vb[2 * pr][1], vb[2 * pr + 1][0], vb[2 * pr + 1][1],
                       smem_u32(cV + r * 72 + c));
            }
#pragma unroll
            for (int nt = 0; nt < 8; nt++) mma16816(o[nt], ap, vb[nt]);
        }
    }

    // reduce softmax denominator across the 4 threads sharing a q-row
    l0 += __shfl_xor_sync(0xffffffffu, l0, 1);
    l0 += __shfl_xor_sync(0xffffffffu, l0, 2);
    l1 += __shfl_xor_sync(0xffffffffu, l1, 1);
    l1 += __shfl_xor_sync(0xffffffffu, l1, 2);

    // ---- normalize + write y (fp16) ----
    const float il0 = 1.f / l0, il1 = 1.f / l1;
#pragma unroll
    for (int nt = 0; nt < 8; nt++) {
        int row = q0 + wid * 16 + g;
        int col = h * HDIM + nt * 8 + 2 * tg;
        *reinterpret_cast<__half2*>(y + (rb + row) * DMODEL + col) =
            __floats2half2_rn(o[nt][0] * il0, o[nt][1] * il0);
        *reinterpret_cast<__half2*>(y + (rb + row + 8) * DMODEL + col) =
            __floats2half2_rn(o[nt][2] * il1, o[nt][3] * il1);
    }
}

// ---------------- launcher ---------------------------------------------------
extern "C" void kernel_launch(void* const* d_in, const int* in_sizes, int n_in,
                              void* d_out, int out_size)
{
    (void)in_sizes; (void)n_in; (void)out_size;
    const float* x    = (const float*)d_in[0];
    const float* wqkv = (const float*)d_in[1];
    const float* wo   = (const float*)d_in[2];
    float* out = (float*)d_out;

    __half *xh, *wqkvh, *woh, *qkvh, *yh;
    cudaGetSymbolAddress((void**)&xh,    g_xh);
    cudaGetSymbolAddress((void**)&wqkvh, g_wqkvh);
    cudaGetSymbolAddress((void**)&woh,   g_woh);
    cudaGetSymbolAddress((void**)&qkvh,  g_qkvh);
    cudaGetSymbolAddress((void**)&yh,    g_yh);

    // raise dynamic smem limits (host-side attribute; idempotent, no allocation)
    cudaFuncSetAttribute(gemm_f16<__half>, cudaFuncAttributeMaxDynamicSharedMemorySize, GEMM_SMEM_BYTES);
    cudaFuncSetAttribute(gemm_f16<float>,  cudaFuncAttributeMaxDynamicSharedMemorySize, GEMM_SMEM_BYTES);
    cudaFuncSetAttribute(attn_kernel,      cudaFuncAttributeMaxDynamicSharedMemorySize, ATTN_SMEM_BYTES);

    cvt_kernel<<<512, 256>>>((const float4*)x,    (__half2*)xh,    NROWS * DMODEL / 4);
    cvt_kernel<<<512, 256>>>((const float4*)wqkv, (__half2*)wqkvh, DMODEL * 3 * DMODEL / 4);
    cvt_kernel<<<256, 256>>>((const float4*)wo,   (__half2*)woh,   DMODEL * DMODEL / 4);

    // qkv = x @ Wqkv : [4096,3072]
    gemm_f16<__half><<<dim3(3 * DMODEL / 128, NROWS / 128), 256, GEMM_SMEM_BYTES>>>(
        xh, wqkvh, qkvh, NROWS, 3 * DMODEL, DMODEL);

    // flash attention -> y (fp16) [4096,1024]
    attn_kernel<<<dim3(TDIM / 128, NHEAD, 2), 256, ATTN_SMEM_BYTES>>>(qkvh, yh);

    // out = y @ Wo : [4096,1024] fp32
    gemm_f16<float><<<dim3(DMODEL / 128, NROWS / 128), 256, GEMM_SMEM_BYTES>>>(
        yh, woh, out, NROWS, DMODEL, DMODEL);
}

// round 5
// speedup vs baseline: 1.0434x; 1.0371x over previous
#include <cuda_runtime.h>
#include <cuda_fp16.h>
#include <cstdint>

#define TDIM 2048
#define DMODEL 1024
#define NROWS 4096          // B*T = 2*2048
#define NHEAD 16
#define HDIM 64

// ---------------- scratch (device globals; no allocation allowed) ----------
__device__ __align__(16) __half g_xh   [NROWS * DMODEL];
__device__ __align__(16) __half g_wqkvh[DMODEL * 3 * DMODEL];
__device__ __align__(16) __half g_woh  [DMODEL * DMODEL];
__device__ __align__(16) __half g_qkvh [(size_t)NROWS * 3 * DMODEL];
__device__ __align__(16) __half g_yh   [NROWS * DMODEL];

// ---------------- small PTX helpers ----------------------------------------
__device__ __forceinline__ uint32_t smem_u32(const void* p) {
    return (uint32_t)__cvta_generic_to_shared(p);
}
__device__ __forceinline__ void cp_async16(uint32_t s, const void* g) {
    asm volatile("cp.async.cg.shared.global [%0], [%1], 16;" ::"r"(s), "l"(g));
}
__device__ __forceinline__ void cp_commit() {
    asm volatile("cp.async.commit_group;");
}
__device__ __forceinline__ void ldsm4(uint32_t& r0, uint32_t& r1, uint32_t& r2, uint32_t& r3, uint32_t a) {
    asm volatile("ldmatrix.sync.aligned.m8n8.x4.shared.b16 {%0,%1,%2,%3}, [%4];"
                 : "=r"(r0), "=r"(r1), "=r"(r2), "=r"(r3) : "r"(a));
}
__device__ __forceinline__ void ldsm4t(uint32_t& r0, uint32_t& r1, uint32_t& r2, uint32_t& r3, uint32_t a) {
    asm volatile("ldmatrix.sync.aligned.m8n8.x4.trans.shared.b16 {%0,%1,%2,%3}, [%4];"
                 : "=r"(r0), "=r"(r1), "=r"(r2), "=r"(r3) : "r"(a));
}
__device__ __forceinline__ void mma16816(float c[4], const uint32_t a[4], const uint32_t b[2]) {
    asm volatile(
        "mma.sync.aligned.m16n8k16.row.col.f32.f16.f16.f32 "
        "{%0,%1,%2,%3}, {%4,%5,%6,%7}, {%8,%9}, {%0,%1,%2,%3};"
        : "+f"(c[0]), "+f"(c[1]), "+f"(c[2]), "+f"(c[3])
        : "r"(a[0]), "r"(a[1]), "r"(a[2]), "r"(a[3]), "r"(b[0]), "r"(b[1]));
}

__device__ __forceinline__ void store2(__half* C, size_t idx, float a, float b) {
    *reinterpret_cast<__half2*>(C + idx) = __floats2half2_rn(a, b);
}
__device__ __forceinline__ void store2(float* C, size_t idx, float a, float b) {
    *reinterpret_cast<float2*>(C + idx) = make_float2(a, b);
}

// ---------------- fp32 -> fp16 conversion -----------------------------------
__global__ void cvt_kernel(const float4* __restrict__ s, __half2* __restrict__ d, int n4) {
    int i = blockIdx.x * blockDim.x + threadIdx.x;
    int stride = gridDim.x * blockDim.x;
    for (; i < n4; i += stride) {
        float4 v = s[i];
        d[2 * i]     = __floats2half2_rn(v.x, v.y);
        d[2 * i + 1] = __floats2half2_rn(v.z, v.w);
    }
}

// ============================================================================
// GEMM v2 (mma.sync path): C[M,N] = A[M,K] * B[K,N], fp16 in, fp32 accum.
// CTA 128x128, 4 warps (2x2), warp tile 64x64, K-tile 64, 3-stage cp.async.
// sA: [128][72] halves per stage (stride 72 -> 9 x 16B, odd: LDSM conflict-free)
// sB: [64][136] halves per stage (stride 136 -> 17 x 16B, odd)
// ============================================================================
#define G_STAGES 3
#define GA_H (128 * 72)
#define GB_H (64 * 136)
#define G_STAGE_H (GA_H + GB_H)
#define GEMM_SMEM_BYTES (G_STAGES * G_STAGE_H * 2)

template <typename OutT>
__global__ void __launch_bounds__(128) gemm_f16(
    const __half* __restrict__ A, const __half* __restrict__ B,
    OutT* __restrict__ C, int M, int N, int K)
{
    extern __shared__ __align__(16) __half smem[];

    const int tid   = threadIdx.x;
    const int lane  = tid & 31;
    const int wid   = tid >> 5;
    const int warpM = wid >> 1;       // 0..1
    const int warpN = wid & 1;        // 0..1
    const int g  = lane >> 2, tg = lane & 3;
    const int bm = blockIdx.y * 128, bn = blockIdx.x * 128;

    float acc[4][8][4];
#pragma unroll
    for (int i = 0; i < 4; i++)
#pragma unroll
        for (int j = 0; j < 8; j++)
#pragma unroll
            for (int k = 0; k < 4; k++) acc[i][j][k] = 0.f;

    const int KT = K >> 6;   // 64-wide K tiles

    // per-thread load coords
    const int am = tid >> 3, ak = (tid & 7) * 8;     // A: 128 rows x 64 cols, 8x16B/thread
    const int bk = tid >> 4, bnc = (tid & 15) * 8;   // B: 64 rows x 128 cols, 8x16B/thread... (strided over i)

    auto load_tile = [&](int kt, int st) {
        __half* sA = smem + st * G_STAGE_H;
        __half* sB = sA + GA_H;
        const int k0 = kt * 64;
        // A: thread covers row am (one row), cols ak..ak+7  -> need all 128 rows: i strides rows by 16
#pragma unroll
        for (int i = 0; i < 8; i++) {
            int m = am + i * 16;
            cp_async16(smem_u32(sA + m * 72 + ak),
                       A + (size_t)(bm + m) * K + k0 + ak);
        }
        // B: thread covers row bk (of 64), cols bnc..bnc+7 for half the cols; i strides rows by 8
#pragma unroll
        for (int i = 0; i < 8; i++) {
            int k = bk + i * 8;
            cp_async16(smem_u32(sB + k * 136 + bnc),
                       B + (size_t)(k0 + k) * N + bn + bnc);
        }
    };

    // prologue: stages 0 .. G_STAGES-2
    load_tile(0, 0); cp_commit();
    if (KT > 1) load_tile(1, 1);
    cp_commit();

    for (int kt = 0; kt < KT; ++kt) {
        asm volatile("cp.async.wait_group %0;" ::"n"(G_STAGES - 2));
        __syncthreads();

        // prefetch stage kt + G_STAGES-1
        {
            const int pf = kt + G_STAGES - 1;
            if (pf < KT) load_tile(pf, pf % G_STAGES);
            cp_commit();
        }

        const __half* cA = smem + (kt % G_STAGES) * G_STAGE_H;
        const __half* cB = cA + GA_H;

#pragma unroll
        for (int ks = 0; ks < 4; ++ks) {
            uint32_t af[4][4], bf[8][2];
#pragma unroll
            for (int mi = 0; mi < 4; mi++) {
                int r = warpM * 64 + mi * 16 + (lane & 7) + ((lane >> 3) & 1) * 8;
                int c = ks * 16 + (lane >> 4) * 8;
                ldsm4(af[mi][0], af[mi][1], af[mi][2], af[mi][3],
                      smem_u32(cA + r * 72 + c));
            }
#pragma unroll
            for (int pr = 0; pr < 4; pr++) {
                int r = ks * 16 + (lane & 7) + ((lane >> 3) & 1) * 8;
                int c = warpN * 64 + pr * 16 + (lane >> 4) * 8;
                ldsm4t(bf[2 * pr][0], bf[2 * pr][1], bf[2 * pr + 1][0], bf[2 * pr + 1][1],
                       smem_u32(cB + r * 136 + c));
            }
#pragma unroll
            for (int mi = 0; mi < 4; mi++)
#pragma unroll
                for (int ni = 0; ni < 8; ni++) mma16816(acc[mi][ni], af[mi], bf[ni]);
        }
    }

    // epilogue
#pragma unroll
    for (int mi = 0; mi < 4; mi++) {
#pragma unroll
        for (int ni = 0; ni < 8; ni++) {
            int row = bm + warpM * 64 + mi * 16 + g;
            int col = bn + warpN * 64 + ni * 8 + 2 * tg;
            store2(C, (size_t)row * N + col, acc[mi][ni][0], acc[mi][ni][1]);
            store2(C, (size_t)(row + 8) * N + col, acc[mi][ni][2], acc[mi][ni][3]);
        }
    }
}

// ---------------- flash attention (unchanged, HMMA path) --------------------
#define A_STAGES 3
#define AK_H (64 * 72)
#define ATTN_SMEM_BYTES (A_STAGES * 2 * AK_H * 2)

__global__ void __launch_bounds__(256) attn_kernel(
    const __half* __restrict__ qkv, __half* __restrict__ y)
{
    extern __shared__ __align__(16) __half smemh[];
    __half* sK = smemh;
    __half* sV = smemh + A_STAGES * AK_H;

    const int tid = threadIdx.x, lane = tid & 31, wid = tid >> 5;
    const int g = lane >> 2, tg = lane & 3;
    const int h = blockIdx.y, b = blockIdx.z;
    const int q0 = blockIdx.x * 128;
    const size_t rb = (size_t)b * TDIM;
    const int qoff = h * HDIM, koff = DMODEL + h * HDIM, voff = 2 * DMODEL + h * HDIM;
    const int S3 = 3 * DMODEL;

    uint32_t qa[4][4];
    {
        __half* qs = sK;
        const int r = tid >> 3, c = (tid & 7) * 8;
#pragma unroll
        for (int p = 0; p < 4; p++)
            cp_async16(smem_u32(qs + (r + p * 32) * 72 + c),
                       qkv + (rb + q0 + r + p * 32) * S3 + qoff + c);
        cp_commit();
        asm volatile("cp.async.wait_group 0;");
        __syncthreads();
#pragma unroll
        for (int ks = 0; ks < 4; ks++) {
            int rr = wid * 16 + (lane & 7) + ((lane >> 3) & 1) * 8;
            int cc = ks * 16 + (lane >> 4) * 8;
            ldsm4(qa[ks][0], qa[ks][1], qa[ks][2], qa[ks][3],
                  smem_u32(qs + rr * 72 + cc));
        }
        __syncthreads();
    }

    float o[8][4];
#pragma unroll
    for (int i = 0; i < 8; i++)
#pragma unroll
        for (int j = 0; j < 4; j++) o[i][j] = 0.f;
    float m0 = -1e30f, m1 = -1e30f, l0 = 0.f, l1 = 0.f;

    const int lr = tid >> 3, lc = (tid & 7) * 8;
#pragma unroll
    for (int st = 0; st < A_STAGES - 1; st++) {
        const int kv0 = st * 64;
#pragma unroll
        for (int p = 0; p < 2; p++) {
            cp_async16(smem_u32(sK + st * AK_H + (lr + p * 32) * 72 + lc),
                       qkv + (rb + kv0 + lr + p * 32) * S3 + koff + lc);
            cp_async16(smem_u32(sV + st * AK_H + (lr + p * 32) * 72 + lc),
                       qkv + (rb + kv0 + lr + p * 32) * S3 + voff + lc);
        }
        cp_commit();
    }

    const int NT = TDIM / 64;
    for (int it = 0; it < NT; ++it) {
        asm volatile("cp.async.wait_group %0;" ::"n"(A_STAGES - 2));
        __syncthreads();
        {
            const int pf = it + A_STAGES - 1;
            if (pf < NT) {
                const int st = pf % A_STAGES, kv0 = pf * 64;
#pragma unroll
                for (int p = 0; p < 2; p++) {
                    cp_async16(smem_u32(sK + st * AK_H + (lr + p * 32) * 72 + lc),
                               qkv + (rb + kv0 + lr + p * 32) * S3 + koff + lc);
                    cp_async16(smem_u32(sV + st * AK_H + (lr + p * 32) * 72 + lc),
                               qkv + (rb + kv0 + lr + p * 32) * S3 + voff + lc);
                }
            }
            cp_commit();
        }

        const int st = it % A_STAGES;
        const __half* cK = sK + st * AK_H;
        const __half* cV = sV + st * AK_H;

        float s[8][4];
#pragma unroll
        for (int i = 0; i < 8; i++)
#pragma unroll
            for (int j = 0; j < 4; j++) s[i][j] = 0.f;

#pragma unroll
        for (int ks = 0; ks < 4; ks++) {
            uint32_t kb[8][2];
#pragma unroll
            for (int pr = 0; pr < 4; pr++) {
                int r = pr * 16 + (lane >> 4) * 8 + (lane & 7);
                int c = ks * 16 + ((lane >> 3) & 1) * 8;
                ldsm4(kb[2 * pr][0], kb[2 * pr][1], kb[2 * pr + 1][0], kb[2 * pr + 1][1],
                      smem_u32(cK + r * 72 + c));
            }
#pragma unroll
            for (int nt = 0; nt < 8; nt++) mma16816(s[nt], qa[ks], kb[nt]);
        }

        const float cs = 0.18033688011112042f;
        float mt0 = -1e30f, mt1 = -1e30f;
#pragma unroll
        for (int nt = 0; nt < 8; nt++) {
            mt0 = fmaxf(mt0, fmaxf(s[nt][0], s[nt][1]));
            mt1 = fmaxf(mt1, fmaxf(s[nt][2], s[nt][3]));
        }
        mt0 = fmaxf(mt0, __shfl_xor_sync(0xffffffffu, mt0, 1));
        mt0 = fmaxf(mt0, __shfl_xor_sync(0xffffffffu, mt0, 2));
        mt1 = fmaxf(mt1, __shfl_xor_sync(0xffffffffu, mt1, 1));
        mt1 = fmaxf(mt1, __shfl_xor_sync(0xffffffffu, mt1, 2));
        float mn0 = fmaxf(m0, mt0 * cs);
        float mn1 = fmaxf(m1, mt1 * cs);
        float a0 = exp2f(m0 - mn0), a1 = exp2f(m1 - mn1);
        float rs0 = 0.f, rs1 = 0.f;
        uint32_t pa[8][2];
#pragma unroll
        for (int nt = 0; nt < 8; nt++) {
            float p0 = exp2f(s[nt][0] * cs - mn0);
            float p1 = exp2f(s[nt][1] * cs - mn0);
            float p2 = exp2f(s[nt][2] * cs - mn1);
            float p3 = exp2f(s[nt][3] * cs - mn1);
            rs0 += p0 + p1;
            rs1 += p2 + p3;
            __half2 h01 = __floats2half2_rn(p0, p1);
            __half2 h23 = __floats2half2_rn(p2, p3);
            pa[nt][0] = *reinterpret_cast<uint32_t*>(&h01);
            pa[nt][1] = *reinterpret_cast<uint32_t*>(&h23);
        }
        m0 = mn0; m1 = mn1;
        l0 = l0 * a0 + rs0;
        l1 = l1 * a1 + rs1;
#pragma unroll
        for (int nt = 0; nt < 8; nt++) {
            o[nt][0] *= a0; o[nt][1] *= a0;
            o[nt][2] *= a1; o[nt][3] *= a1;
        }

#pragma unroll
        for (int ks = 0; ks < 4; ks++) {
            uint32_t ap[4] = { pa[2 * ks][0], pa[2 * ks][1], pa[2 * ks + 1][0], pa[2 * ks + 1][1] };
            uint32_t vb[8][2];
#pragma unroll
            for (int pr = 0; pr < 4; pr++) {
                int r = ks * 16 + ((lane >> 3) & 1) * 8 + (lane & 7);
                int c = pr * 16 + (lane >> 4) * 8;
                ldsm4t(vb[2 * pr][0], vb[2 * pr][1], vb[2 * pr + 1][0], vb[2 * pr + 1][1],
                       smem_u32(cV + r * 72 + c));
            }
#pragma unroll
            for (int nt = 0; nt < 8; nt++) mma16816(o[nt], ap, vb[nt]);
        }
    }

    l0 += __shfl_xor_sync(0xffffffffu, l0, 1);
    l0 += __shfl_xor_sync(0xffffffffu, l0, 2);
    l1 += __shfl_xor_sync(0xffffffffu, l1, 1);
    l1 += __shfl_xor_sync(0xffffffffu, l1, 2);

    const float il0 = 1.f / l0, il1 = 1.f / l1;
#pragma unroll
    for (int nt = 0; nt < 8; nt++) {
        int row = q0 + wid * 16 + g;
        int col = h * HDIM + nt * 8 + 2 * tg;
        *reinterpret_cast<__half2*>(y + (rb + row) * DMODEL + col) =
            __floats2half2_rn(o[nt][0] * il0, o[nt][1] * il0);
        *reinterpret_cast<__half2*>(y + (rb + row + 8) * DMODEL + col) =
            __floats2half2_rn(o[nt][2] * il1, o[nt][3] * il1);
    }
}

// ---------------- launcher ---------------------------------------------------
extern "C" void kernel_launch(void* const* d_in, const int* in_sizes, int n_in,
                              void* d_out, int out_size)
{
    (void)in_sizes; (void)n_in; (void)out_size;
    const float* x    = (const float*)d_in[0];
    const float* wqkv = (const float*)d_in[1];
    const float* wo   = (const float*)d_in[2];
    float* out = (float*)d_out;

    __half *xh, *wqkvh, *woh, *qkvh, *yh;
    cudaGetSymbolAddress((void**)&xh,    g_xh);
    cudaGetSymbolAddress((void**)&wqkvh, g_wqkvh);
    cudaGetSymbolAddress((void**)&woh,   g_woh);
    cudaGetSymbolAddress((void**)&qkvh,  g_qkvh);
    cudaGetSymbolAddress((void**)&yh,    g_yh);

    cudaFuncSetAttribute(gemm_f16<__half>, cudaFuncAttributeMaxDynamicSharedMemorySize, GEMM_SMEM_BYTES);
    cudaFuncSetAttribute(gemm_f16<float>,  cudaFuncAttributeMaxDynamicSharedMemorySize, GEMM_SMEM_BYTES);
    cudaFuncSetAttribute(attn_kernel,      cudaFuncAttributeMaxDynamicSharedMemorySize, ATTN_SMEM_BYTES);

    cvt_kernel<<<512, 256>>>((const float4*)x,    (__half2*)xh,    NROWS * DMODEL / 4);
    cvt_kernel<<<512, 256>>>((const float4*)wqkv, (__half2*)wqkvh, DMODEL * 3 * DMODEL / 4);
    cvt_kernel<<<256, 256>>>((const float4*)wo,   (__half2*)woh,   DMODEL * DMODEL / 4);

    // qkv = x @ Wqkv : [4096,3072]
    gemm_f16<__half><<<dim3(3 * DMODEL / 128, NROWS / 128), 128, GEMM_SMEM_BYTES>>>(
        xh, wqkvh, qkvh, NROWS, 3 * DMODEL, DMODEL);

    // flash attention -> y (fp16) [4096,1024]
    attn_kernel<<<dim3(TDIM / 128, NHEAD, 2), 256, ATTN_SMEM_BYTES>>>(qkvh, yh);

    // out = y @ Wo : [4096,1024] fp32
    gemm_f16<float><<<dim3(DMODEL / 128, NROWS / 128), 128, GEMM_SMEM_BYTES>>>(
        yh, woh, out, NROWS, DMODEL, DMODEL);
}

// round 6
// speedup vs baseline: 1.0683x; 1.0239x over previous
#include <cuda_runtime.h>
#include <cuda_fp16.h>
#include <cstdint>

#define TDIM 2048
#define DMODEL 1024
#define NROWS 4096          // B*T = 2*2048
#define NHEAD 16
#define HDIM 64

// ---------------- scratch (device globals; no allocation allowed) ----------
__device__ __align__(16) __half g_xh   [NROWS * DMODEL];
__device__ __align__(16) __half g_wqkvh[DMODEL * 3 * DMODEL];
__device__ __align__(16) __half g_woh  [DMODEL * DMODEL];
__device__ __align__(16) __half g_qkvh [(size_t)NROWS * 3 * DMODEL];
__device__ __align__(16) __half g_yh   [NROWS * DMODEL];

// ---------------- small PTX helpers ----------------------------------------
__device__ __forceinline__ uint32_t smem_u32(const void* p) {
    return (uint32_t)__cvta_generic_to_shared(p);
}
__device__ __forceinline__ void cp_async16(uint32_t s, const void* g) {
    asm volatile("cp.async.cg.shared.global [%0], [%1], 16;" ::"r"(s), "l"(g));
}
__device__ __forceinline__ void cp_commit() {
    asm volatile("cp.async.commit_group;");
}
__device__ __forceinline__ void ldsm4(uint32_t& r0, uint32_t& r1, uint32_t& r2, uint32_t& r3, uint32_t a) {
    asm volatile("ldmatrix.sync.aligned.m8n8.x4.shared.b16 {%0,%1,%2,%3}, [%4];"
                 : "=r"(r0), "=r"(r1), "=r"(r2), "=r"(r3) : "r"(a));
}
__device__ __forceinline__ void ldsm4t(uint32_t& r0, uint32_t& r1, uint32_t& r2, uint32_t& r3, uint32_t a) {
    asm volatile("ldmatrix.sync.aligned.m8n8.x4.trans.shared.b16 {%0,%1,%2,%3}, [%4];"
                 : "=r"(r0), "=r"(r1), "=r"(r2), "=r"(r3) : "r"(a));
}
__device__ __forceinline__ void mma16816(float c[4], const uint32_t a[4], const uint32_t b[2]) {
    asm volatile(
        "mma.sync.aligned.m16n8k16.row.col.f32.f16.f16.f32 "
        "{%0,%1,%2,%3}, {%4,%5,%6,%7}, {%8,%9}, {%0,%1,%2,%3};"
        : "+f"(c[0]), "+f"(c[1]), "+f"(c[2]), "+f"(c[3])
        : "r"(a[0]), "r"(a[1]), "r"(a[2]), "r"(a[3]), "r"(b[0]), "r"(b[1]));
}

__device__ __forceinline__ void store2(__half* C, size_t idx, float a, float b) {
    *reinterpret_cast<__half2*>(C + idx) = __floats2half2_rn(a, b);
}
__device__ __forceinline__ void store2(float* C, size_t idx, float a, float b) {
    *reinterpret_cast<float2*>(C + idx) = make_float2(a, b);
}

// ---------------- fp32 -> fp16 conversion -----------------------------------
__global__ void cvt_kernel(const float4* __restrict__ s, __half2* __restrict__ d, int n4) {
    int i = blockIdx.x * blockDim.x + threadIdx.x;
    int stride = gridDim.x * blockDim.x;
    for (; i < n4; i += stride) {
        float4 v = s[i];
        d[2 * i]     = __floats2half2_rn(v.x, v.y);
        d[2 * i + 1] = __floats2half2_rn(v.z, v.w);
    }
}

// ============================================================================
// GEMM v3 (mma.sync path): C[M,N] = A[M,K] * B[K,N], fp16 in, fp32 accum.
// CTA 256x128, 8 warps (4x2), warp tile 64x64 -> 2 warps/SMSP to hide LDS
// latency while keeping mma:ldsm = 4:1. K-tile 64, 3-stage cp.async.
// sA: [256][72] halves per stage; sB: [64][136] halves per stage.
// ============================================================================
#define G_STAGES 3
#define GA_H (256 * 72)
#define GB_H (64 * 136)
#define G_STAGE_H (GA_H + GB_H)
#define GEMM_SMEM_BYTES (G_STAGES * G_STAGE_H * 2)

template <typename OutT>
__global__ void __launch_bounds__(256) gemm_f16(
    const __half* __restrict__ A, const __half* __restrict__ B,
    OutT* __restrict__ C, int M, int N, int K)
{
    extern __shared__ __align__(16) __half smem[];

    const int tid   = threadIdx.x;
    const int lane  = tid & 31;
    const int wid   = tid >> 5;
    const int warpM = wid >> 1;       // 0..3
    const int warpN = wid & 1;        // 0..1
    const int g  = lane >> 2, tg = lane & 3;
    const int bm = blockIdx.y * 256, bn = blockIdx.x * 128;

    float acc[4][8][4];
#pragma unroll
    for (int i = 0; i < 4; i++)
#pragma unroll
        for (int j = 0; j < 8; j++)
#pragma unroll
            for (int k = 0; k < 4; k++) acc[i][j][k] = 0.f;

    const int KT = K >> 6;   // 64-wide K tiles

    auto load_tile = [&](int kt, int st) {
        __half* sA = smem + st * G_STAGE_H;
        __half* sB = sA + GA_H;
        const int k0 = kt * 64;
        // A tile 256x64: 2048 x 16B chunks, 8 per thread
#pragma unroll
        for (int i = 0; i < 8; i++) {
            int idx = tid + i * 256;
            int m = idx >> 3, k8 = (idx & 7) * 8;
            cp_async16(smem_u32(sA + m * 72 + k8),
                       A + (size_t)(bm + m) * K + k0 + k8);
        }
        // B tile 64x128: 1024 x 16B chunks, 4 per thread
#pragma unroll
        for (int i = 0; i < 4; i++) {
            int idx = tid + i * 256;
            int k = idx >> 4, nc = (idx & 15) * 8;
            cp_async16(smem_u32(sB + k * 136 + nc),
                       B + (size_t)(k0 + k) * N + bn + nc);
        }
    };

    // prologue: stages 0 .. G_STAGES-2
    load_tile(0, 0); cp_commit();
    if (KT > 1) load_tile(1, 1);
    cp_commit();

    for (int kt = 0; kt < KT; ++kt) {
        asm volatile("cp.async.wait_group %0;" ::"n"(G_STAGES - 2));
        __syncthreads();

        // prefetch stage kt + G_STAGES-1
        {
            const int pf = kt + G_STAGES - 1;
            if (pf < KT) load_tile(pf, pf % G_STAGES);
            cp_commit();
        }

        const __half* cA = smem + (kt % G_STAGES) * G_STAGE_H;
        const __half* cB = cA + GA_H;

#pragma unroll
        for (int ks = 0; ks < 4; ++ks) {
            uint32_t af[4][4], bf[8][2];
#pragma unroll
            for (int mi = 0; mi < 4; mi++) {
                int r = warpM * 64 + mi * 16 + (lane & 7) + ((lane >> 3) & 1) * 8;
                int c = ks * 16 + (lane >> 4) * 8;
                ldsm4(af[mi][0], af[mi][1], af[mi][2], af[mi][3],
                      smem_u32(cA + r * 72 + c));
            }
#pragma unroll
            for (int pr = 0; pr < 4; pr++) {
                int r = ks * 16 + (lane & 7) + ((lane >> 3) & 1) * 8;
                int c = warpN * 64 + pr * 16 + (lane >> 4) * 8;
                ldsm4t(bf[2 * pr][0], bf[2 * pr][1], bf[2 * pr + 1][0], bf[2 * pr + 1][1],
                       smem_u32(cB + r * 136 + c));
            }
#pragma unroll
            for (int mi = 0; mi < 4; mi++)
#pragma unroll
                for (int ni = 0; ni < 8; ni++) mma16816(acc[mi][ni], af[mi], bf[ni]);
        }
    }

    // epilogue
#pragma unroll
    for (int mi = 0; mi < 4; mi++) {
#pragma unroll
        for (int ni = 0; ni < 8; ni++) {
            int row = bm + warpM * 64 + mi * 16 + g;
            int col = bn + warpN * 64 + ni * 8 + 2 * tg;
            store2(C, (size_t)row * N + col, acc[mi][ni][0], acc[mi][ni][1]);
            store2(C, (size_t)(row + 8) * N + col, acc[mi][ni][2], acc[mi][ni][3]);
        }
    }
}

// ---------------- flash attention (unchanged, HMMA path) --------------------
#define A_STAGES 3
#define AK_H (64 * 72)
#define ATTN_SMEM_BYTES (A_STAGES * 2 * AK_H * 2)

__global__ void __launch_bounds__(256) attn_kernel(
    const __half* __restrict__ qkv, __half* __restrict__ y)
{
    extern __shared__ __align__(16) __half smemh[];
    __half* sK = smemh;
    __half* sV = smemh + A_STAGES * AK_H;

    const int tid = threadIdx.x, lane = tid & 31, wid = tid >> 5;
    const int g = lane >> 2, tg = lane & 3;
    const int h = blockIdx.y, b = blockIdx.z;
    const int q0 = blockIdx.x * 128;
    const size_t rb = (size_t)b * TDIM;
    const int qoff = h * HDIM, koff = DMODEL + h * HDIM, voff = 2 * DMODEL + h * HDIM;
    const int S3 = 3 * DMODEL;

    uint32_t qa[4][4];
    {
        __half* qs = sK;
        const int r = tid >> 3, c = (tid & 7) * 8;
#pragma unroll
        for (int p = 0; p < 4; p++)
            cp_async16(smem_u32(qs + (r + p * 32) * 72 + c),
                       qkv + (rb + q0 + r + p * 32) * S3 + qoff + c);
        cp_commit();
        asm volatile("cp.async.wait_group 0;");
        __syncthreads();
#pragma unroll
        for (int ks = 0; ks < 4; ks++) {
            int rr = wid * 16 + (lane & 7) + ((lane >> 3) & 1) * 8;
            int cc = ks * 16 + (lane >> 4) * 8;
            ldsm4(qa[ks][0], qa[ks][1], qa[ks][2], qa[ks][3],
                  smem_u32(qs + rr * 72 + cc));
        }
        __syncthreads();
    }

    float o[8][4];
#pragma unroll
    for (int i = 0; i < 8; i++)
#pragma unroll
        for (int j = 0; j < 4; j++) o[i][j] = 0.f;
    float m0 = -1e30f, m1 = -1e30f, l0 = 0.f, l1 = 0.f;

    const int lr = tid >> 3, lc = (tid & 7) * 8;
#pragma unroll
    for (int st = 0; st < A_STAGES - 1; st++) {
        const int kv0 = st * 64;
#pragma unroll
        for (int p = 0; p < 2; p++) {
            cp_async16(smem_u32(sK + st * AK_H + (lr + p * 32) * 72 + lc),
                       qkv + (rb + kv0 + lr + p * 32) * S3 + koff + lc);
            cp_async16(smem_u32(sV + st * AK_H + (lr + p * 32) * 72 + lc),
                       qkv + (rb + kv0 + lr + p * 32) * S3 + voff + lc);
        }
        cp_commit();
    }

    const int NT = TDIM / 64;
    for (int it = 0; it < NT; ++it) {
        asm volatile("cp.async.wait_group %0;" ::"n"(A_STAGES - 2));
        __syncthreads();
        {
            const int pf = it + A_STAGES - 1;
            if (pf < NT) {
                const int st = pf % A_STAGES, kv0 = pf * 64;
#pragma unroll
                for (int p = 0; p < 2; p++) {
                    cp_async16(smem_u32(sK + st * AK_H + (lr + p * 32) * 72 + lc),
                               qkv + (rb + kv0 + lr + p * 32) * S3 + koff + lc);
                    cp_async16(smem_u32(sV + st * AK_H + (lr + p * 32) * 72 + lc),
                               qkv + (rb + kv0 + lr + p * 32) * S3 + voff + lc);
                }
            }
            cp_commit();
        }

        const int st = it % A_STAGES;
        const __half* cK = sK + st * AK_H;
        const __half* cV = sV + st * AK_H;

        float s[8][4];
#pragma unroll
        for (int i = 0; i < 8; i++)
#pragma unroll
            for (int j = 0; j < 4; j++) s[i][j] = 0.f;

#pragma unroll
        for (int ks = 0; ks < 4; ks++) {
            uint32_t kb[8][2];
#pragma unroll
            for (int pr = 0; pr < 4; pr++) {
                int r = pr * 16 + (lane >> 4) * 8 + (lane & 7);
                int c = ks * 16 + ((lane >> 3) & 1) * 8;
                ldsm4(kb[2 * pr][0], kb[2 * pr][1], kb[2 * pr + 1][0], kb[2 * pr + 1][1],
                      smem_u32(cK + r * 72 + c));
            }
#pragma unroll
            for (int nt = 0; nt < 8; nt++) mma16816(s[nt], qa[ks], kb[nt]);
        }

        const float cs = 0.18033688011112042f;
        float mt0 = -1e30f, mt1 = -1e30f;
#pragma unroll
        for (int nt = 0; nt < 8; nt++) {
            mt0 = fmaxf(mt0, fmaxf(s[nt][0], s[nt][1]));
            mt1 = fmaxf(mt1, fmaxf(s[nt][2], s[nt][3]));
        }
        mt0 = fmaxf(mt0, __shfl_xor_sync(0xffffffffu, mt0, 1));
        mt0 = fmaxf(mt0, __shfl_xor_sync(0xffffffffu, mt0, 2));
        mt1 = fmaxf(mt1, __shfl_xor_sync(0xffffffffu, mt1, 1));
        mt1 = fmaxf(mt1, __shfl_xor_sync(0xffffffffu, mt1, 2));
        float mn0 = fmaxf(m0, mt0 * cs);
        float mn1 = fmaxf(m1, mt1 * cs);
        float a0 = exp2f(m0 - mn0), a1 = exp2f(m1 - mn1);
        float rs0 = 0.f, rs1 = 0.f;
        uint32_t pa[8][2];
#pragma unroll
        for (int nt = 0; nt < 8; nt++) {
            float p0 = exp2f(s[nt][0] * cs - mn0);
            float p1 = exp2f(s[nt][1] * cs - mn0);
            float p2 = exp2f(s[nt][2] * cs - mn1);
            float p3 = exp2f(s[nt][3] * cs - mn1);
            rs0 += p0 + p1;
            rs1 += p2 + p3;
            __half2 h01 = __floats2half2_rn(p0, p1);
            __half2 h23 = __floats2half2_rn(p2, p3);
            pa[nt][0] = *reinterpret_cast<uint32_t*>(&h01);
            pa[nt][1] = *reinterpret_cast<uint32_t*>(&h23);
        }
        m0 = mn0; m1 = mn1;
        l0 = l0 * a0 + rs0;
        l1 = l1 * a1 + rs1;
#pragma unroll
        for (int nt = 0; nt < 8; nt++) {
            o[nt][0] *= a0; o[nt][1] *= a0;
            o[nt][2] *= a1; o[nt][3] *= a1;
        }

#pragma unroll
        for (int ks = 0; ks < 4; ks++) {
            uint32_t ap[4] = { pa[2 * ks][0], pa[2 * ks][1], pa[2 * ks + 1][0], pa[2 * ks + 1][1] };
            uint32_t vb[8][2];
#pragma unroll
            for (int pr = 0; pr < 4; pr++) {
                int r = ks * 16 + ((lane >> 3) & 1) * 8 + (lane & 7);
                int c = pr * 16 + (lane >> 4) * 8;
                ldsm4t(vb[2 * pr][0], vb[2 * pr][1], vb[2 * pr + 1][0], vb[2 * pr + 1][1],
                       smem_u32(cV + r * 72 + c));
            }
#pragma unroll
            for (int nt = 0; nt < 8; nt++) mma16816(o[nt], ap, vb[nt]);
        }
    }

    l0 += __shfl_xor_sync(0xffffffffu, l0, 1);
    l0 += __shfl_xor_sync(0xffffffffu, l0, 2);
    l1 += __shfl_xor_sync(0xffffffffu, l1, 1);
    l1 += __shfl_xor_sync(0xffffffffu, l1, 2);

    const float il0 = 1.f / l0, il1 = 1.f / l1;
#pragma unroll
    for (int nt = 0; nt < 8; nt++) {
        int row = q0 + wid * 16 + g;
        int col = h * HDIM + nt * 8 + 2 * tg;
        *reinterpret_cast<__half2*>(y + (rb + row) * DMODEL + col) =
            __floats2half2_rn(o[nt][0] * il0, o[nt][1] * il0);
        *reinterpret_cast<__half2*>(y + (rb + row + 8) * DMODEL + col) =
            __floats2half2_rn(o[nt][2] * il1, o[nt][3] * il1);
    }
}

// ---------------- launcher ---------------------------------------------------
extern "C" void kernel_launch(void* const* d_in, const int* in_sizes, int n_in,
                              void* d_out, int out_size)
{
    (void)in_sizes; (void)n_in; (void)out_size;
    const float* x    = (const float*)d_in[0];
    const float* wqkv = (const float*)d_in[1];
    const float* wo   = (const float*)d_in[2];
    float* out = (float*)d_out;

    __half *xh, *wqkvh, *woh, *qkvh, *yh;
    cudaGetSymbolAddress((void**)&xh,    g_xh);
    cudaGetSymbolAddress((void**)&wqkvh, g_wqkvh);
    cudaGetSymbolAddress((void**)&woh,   g_woh);
    cudaGetSymbolAddress((void**)&qkvh,  g_qkvh);
    cudaGetSymbolAddress((void**)&yh,    g_yh);

    cudaFuncSetAttribute(gemm_f16<__half>, cudaFuncAttributeMaxDynamicSharedMemorySize, GEMM_SMEM_BYTES);
    cudaFuncSetAttribute(gemm_f16<float>,  cudaFuncAttributeMaxDynamicSharedMemorySize, GEMM_SMEM_BYTES);
    cudaFuncSetAttribute(attn_kernel,      cudaFuncAttributeMaxDynamicSharedMemorySize, ATTN_SMEM_BYTES);

    cvt_kernel<<<512, 256>>>((const float4*)x,    (__half2*)xh,    NROWS * DMODEL / 4);
    cvt_kernel<<<512, 256>>>((const float4*)wqkv, (__half2*)wqkvh, DMODEL * 3 * DMODEL / 4);
    cvt_kernel<<<256, 256>>>((const float4*)wo,   (__half2*)woh,   DMODEL * DMODEL / 4);

    // qkv = x @ Wqkv : [4096,3072]
    gemm_f16<__half><<<dim3(3 * DMODEL / 128, NROWS / 256), 256, GEMM_SMEM_BYTES>>>(
        xh, wqkvh, qkvh, NROWS, 3 * DMODEL, DMODEL);

    // flash attention -> y (fp16) [4096,1024]
    attn_kernel<<<dim3(TDIM / 128, NHEAD, 2), 256, ATTN_SMEM_BYTES>>>(qkvh, yh);

    // out = y @ Wo : [4096,1024] fp32
    gemm_f16<float><<<dim3(DMODEL / 128, NROWS / 256), 256, GEMM_SMEM_BYTES>>>(
        yh, woh, out, NROWS, DMODEL, DMODEL);
}